// round 1
// baseline (speedup 1.0000x reference)
#include <cuda_runtime.h>
#include <cuda_bf16.h>

#define N_BUILD 1048576
#define N_CABLE 50000
#define N_TRANS 2000
#define D 128
#define WPAD 132   // padded smem row stride for transposed weights
#define MTILE 64
#define NTHREADS 256

// Scratch (device globals: no allocation allowed)
__device__ float g_sum_c[N_CABLE * D];
__device__ int   g_cnt_c[N_CABLE];
__device__ float g_sum_t[N_TRANS * D];
__device__ int   g_cnt_t[N_TRANS];

// ---------- packed f32x2 helpers (Blackwell fma.rn.f32x2) ----------
__device__ __forceinline__ unsigned long long pack2(float lo, float hi) {
    unsigned long long r;
    asm("mov.b64 %0, {%1, %2};" : "=l"(r) : "f"(lo), "f"(hi));
    return r;
}
__device__ __forceinline__ void unpack2(unsigned long long v, float& lo, float& hi) {
    asm("mov.b64 {%0, %1}, %2;" : "=f"(lo), "=f"(hi) : "l"(v));
}
__device__ __forceinline__ unsigned long long fma2(unsigned long long a, unsigned long long b, unsigned long long c) {
    unsigned long long d;
    asm("fma.rn.f32x2 %0, %1, %2, %3;" : "=l"(d) : "l"(a), "l"(b), "l"(c));
    return d;
}
__device__ __forceinline__ void red_add_v4(float* p, float a, float b, float c, float d) {
    asm volatile("red.global.add.v4.f32 [%0], {%1, %2, %3, %4};"
                 :: "l"(p), "f"(a), "f"(b), "f"(c), "f"(d) : "memory");
}

// ---------- zero scratch ----------
__global__ void zero_kernel() {
    int stride = gridDim.x * blockDim.x;
    int t = blockIdx.x * blockDim.x + threadIdx.x;
    for (int i = t; i < N_CABLE * D; i += stride) g_sum_c[i] = 0.0f;
    for (int i = t; i < N_TRANS * D; i += stride) g_sum_t[i] = 0.0f;
    for (int i = t; i < N_CABLE; i += stride) g_cnt_c[i] = 0;
    for (int i = t; i < N_TRANS; i += stride) g_cnt_t[i] = 0;
}

// ---------- stage A: MLP(x_building) + scatter-add into cable sums ----------
__global__ __launch_bounds__(NTHREADS)
void stageA(const float* __restrict__ x, const int* __restrict__ abc,
            const float* __restrict__ w1, const float* __restrict__ b1,
            const float* __restrict__ w2, const float* __restrict__ b2) {
    extern __shared__ float sm[];
    float* w1T = sm;                  // [D][WPAD]
    float* w2T = w1T + D * WPAD;      // [D][WPAD]
    float* xs  = w2T + D * WPAD;      // [MTILE][D]
    float* hs  = xs + MTILE * D;      // [MTILE][D]
    __shared__ int cids[MTILE];

    const int tid = threadIdx.x;
    const int tx = tid & 31;
    const int ty = tid >> 5;
    const int c0 = tx * 4;

    // transpose-load both weight matrices once per block
    for (int i = tid; i < D * D; i += NTHREADS) {
        int c = i >> 7, k = i & 127;
        w1T[k * WPAD + c] = w1[i];
        w2T[k * WPAD + c] = w2[i];
    }
    const float4 bias1 = *(const float4*)(b1 + c0);
    const float4 bias2 = *(const float4*)(b2 + c0);

    const int nTiles = N_BUILD / MTILE;
    for (int t = blockIdx.x; t < nTiles; t += gridDim.x) {
        const int base = t * MTILE;
        __syncthreads();  // prior tile fully consumed
        // cooperative load of x tile (one warp covers one row of 32 float4)
        {
            const float4* xg = (const float4*)(x + (long long)base * D);
            float4* xs4 = (float4*)xs;
            #pragma unroll
            for (int i = tid; i < MTILE * (D / 4); i += NTHREADS) xs4[i] = xg[i];
            if (tid < MTILE) cids[tid] = abc[base + tid];
        }
        __syncthreads();

        // GEMM1: h = relu(xs @ w1T + b1), 8 rows x 4 cols per thread
        unsigned long long acc[8][2];
        #pragma unroll
        for (int i = 0; i < 8; i++) { acc[i][0] = 0ULL; acc[i][1] = 0ULL; }
        const float* xrow = xs + ty * 8 * D;
        #pragma unroll 4
        for (int k = 0; k < D; k++) {
            float4 wv = *(const float4*)(w1T + k * WPAD + c0);
            unsigned long long wa = pack2(wv.x, wv.y);
            unsigned long long wb = pack2(wv.z, wv.w);
            #pragma unroll
            for (int i = 0; i < 8; i++) {
                float xv = xrow[i * D + k];
                unsigned long long x2 = pack2(xv, xv);
                acc[i][0] = fma2(x2, wa, acc[i][0]);
                acc[i][1] = fma2(x2, wb, acc[i][1]);
            }
        }
        #pragma unroll
        for (int i = 0; i < 8; i++) {
            float a, b, c, d;
            unpack2(acc[i][0], a, b);
            unpack2(acc[i][1], c, d);
            a = fmaxf(a + bias1.x, 0.0f);
            b = fmaxf(b + bias1.y, 0.0f);
            c = fmaxf(c + bias1.z, 0.0f);
            d = fmaxf(d + bias1.w, 0.0f);
            *(float4*)(hs + (ty * 8 + i) * D + c0) = make_float4(a, b, c, d);
        }
        __syncthreads();

        // GEMM2: y = hs @ w2T + b2
        #pragma unroll
        for (int i = 0; i < 8; i++) { acc[i][0] = 0ULL; acc[i][1] = 0ULL; }
        const float* hrow = hs + ty * 8 * D;
        #pragma unroll 4
        for (int k = 0; k < D; k++) {
            float4 wv = *(const float4*)(w2T + k * WPAD + c0);
            unsigned long long wa = pack2(wv.x, wv.y);
            unsigned long long wb = pack2(wv.z, wv.w);
            #pragma unroll
            for (int i = 0; i < 8; i++) {
                float hv = hrow[i * D + k];
                unsigned long long h2 = pack2(hv, hv);
                acc[i][0] = fma2(h2, wa, acc[i][0]);
                acc[i][1] = fma2(h2, wb, acc[i][1]);
            }
        }
        #pragma unroll
        for (int i = 0; i < 8; i++) {
            float a, b, c, d;
            unpack2(acc[i][0], a, b);
            unpack2(acc[i][1], c, d);
            a += bias2.x; b += bias2.y; c += bias2.z; d += bias2.w;
            int cid = cids[ty * 8 + i];
            red_add_v4(g_sum_c + (long long)cid * D + c0, a, b, c, d);
        }
        if (tx == 0) {
            #pragma unroll
            for (int i = 0; i < 8; i++) atomicAdd(&g_cnt_c[cids[ty * 8 + i]], 1);
        }
    }
}

// ---------- stage B: x_cable = sums/cnt (written to out), MLP(x_cable) + scatter into trans sums ----------
__global__ __launch_bounds__(NTHREADS)
void stageB(const int* __restrict__ act,
            const float* __restrict__ w3, const float* __restrict__ b3,
            const float* __restrict__ w4, const float* __restrict__ b4,
            float* __restrict__ out_cable) {
    extern __shared__ float sm[];
    float* w3T = sm;
    float* w4T = w3T + D * WPAD;
    float* xs  = w4T + D * WPAD;
    float* hs  = xs + MTILE * D;
    __shared__ int tids[MTILE];

    const int tid = threadIdx.x;
    const int tx = tid & 31;
    const int ty = tid >> 5;
    const int c0 = tx * 4;

    for (int i = tid; i < D * D; i += NTHREADS) {
        int c = i >> 7, k = i & 127;
        w3T[k * WPAD + c] = w3[i];
        w4T[k * WPAD + c] = w4[i];
    }
    const float4 bias3 = *(const float4*)(b3 + c0);
    const float4 bias4 = *(const float4*)(b4 + c0);

    const int nTiles = (N_CABLE + MTILE - 1) / MTILE;
    for (int t = blockIdx.x; t < nTiles; t += gridDim.x) {
        const int base = t * MTILE;
        __syncthreads();
        {
            float4* xs4 = (float4*)xs;
            for (int i = tid; i < MTILE * (D / 4); i += NTHREADS) {
                int row = i >> 5, c4 = i & 31;
                int gr = base + row;
                float4 v = make_float4(0.f, 0.f, 0.f, 0.f);
                if (gr < N_CABLE) {
                    float cnt = fmaxf((float)g_cnt_c[gr], 1.0f);
                    float4 s = *(const float4*)(g_sum_c + (long long)gr * D + c4 * 4);
                    v.x = s.x / cnt; v.y = s.y / cnt; v.z = s.z / cnt; v.w = s.w / cnt;
                    *(float4*)(out_cable + (long long)gr * D + c4 * 4) = v;
                }
                xs4[i] = v;
            }
            if (tid < MTILE) {
                int gr = base + tid;
                tids[tid] = (gr < N_CABLE) ? act[gr] : 0;
            }
        }
        __syncthreads();

        unsigned long long acc[8][2];
        #pragma unroll
        for (int i = 0; i < 8; i++) { acc[i][0] = 0ULL; acc[i][1] = 0ULL; }
        const float* xrow = xs + ty * 8 * D;
        #pragma unroll 4
        for (int k = 0; k < D; k++) {
            float4 wv = *(const float4*)(w3T + k * WPAD + c0);
            unsigned long long wa = pack2(wv.x, wv.y);
            unsigned long long wb = pack2(wv.z, wv.w);
            #pragma unroll
            for (int i = 0; i < 8; i++) {
                float xv = xrow[i * D + k];
                unsigned long long x2 = pack2(xv, xv);
                acc[i][0] = fma2(x2, wa, acc[i][0]);
                acc[i][1] = fma2(x2, wb, acc[i][1]);
            }
        }
        #pragma unroll
        for (int i = 0; i < 8; i++) {
            float a, b, c, d;
            unpack2(acc[i][0], a, b);
            unpack2(acc[i][1], c, d);
            a = fmaxf(a + bias3.x, 0.0f);
            b = fmaxf(b + bias3.y, 0.0f);
            c = fmaxf(c + bias3.z, 0.0f);
            d = fmaxf(d + bias3.w, 0.0f);
            *(float4*)(hs + (ty * 8 + i) * D + c0) = make_float4(a, b, c, d);
        }
        __syncthreads();

        #pragma unroll
        for (int i = 0; i < 8; i++) { acc[i][0] = 0ULL; acc[i][1] = 0ULL; }
        const float* hrow = hs + ty * 8 * D;
        #pragma unroll 4
        for (int k = 0; k < D; k++) {
            float4 wv = *(const float4*)(w4T + k * WPAD + c0);
            unsigned long long wa = pack2(wv.x, wv.y);
            unsigned long long wb = pack2(wv.z, wv.w);
            #pragma unroll
            for (int i = 0; i < 8; i++) {
                float hv = hrow[i * D + k];
                unsigned long long h2 = pack2(hv, hv);
                acc[i][0] = fma2(h2, wa, acc[i][0]);
                acc[i][1] = fma2(h2, wb, acc[i][1]);
            }
        }
        #pragma unroll
        for (int i = 0; i < 8; i++) {
            int gr = base + ty * 8 + i;
            if (gr < N_CABLE) {
                float a, b, c, d;
                unpack2(acc[i][0], a, b);
                unpack2(acc[i][1], c, d);
                a += bias4.x; b += bias4.y; c += bias4.z; d += bias4.w;
                int tid2 = tids[ty * 8 + i];
                red_add_v4(g_sum_t + (long long)tid2 * D + c0, a, b, c, d);
            }
        }
        if (tx == 0) {
            #pragma unroll
            for (int i = 0; i < 8; i++) {
                int gr = base + ty * 8 + i;
                if (gr < N_CABLE) atomicAdd(&g_cnt_t[tids[ty * 8 + i]], 1);
            }
        }
    }
}

// ---------- finalize: x_trans = sums_t / max(cnt_t, 1) ----------
__global__ void finalize_trans(float* __restrict__ out_trans) {
    int i = blockIdx.x * blockDim.x + threadIdx.x;
    if (i < N_TRANS * D) {
        int row = i >> 7;
        float cnt = fmaxf((float)g_cnt_t[row], 1.0f);
        out_trans[i] = g_sum_t[i] / cnt;
    }
}

extern "C" void kernel_launch(void* const* d_in, const int* in_sizes, int n_in,
                              void* d_out, int out_size) {
    const float* x   = (const float*)d_in[0];
    const int*   abc = (const int*)d_in[1];
    const int*   act = (const int*)d_in[2];
    const float* w1  = (const float*)d_in[3];
    const float* b1  = (const float*)d_in[4];
    const float* w2  = (const float*)d_in[5];
    const float* b2  = (const float*)d_in[6];
    const float* w3  = (const float*)d_in[7];
    const float* b3  = (const float*)d_in[8];
    const float* w4  = (const float*)d_in[9];
    const float* b4  = (const float*)d_in[10];

    float* out = (float*)d_out;
    float* out_cable = out;                     // [N_CABLE, D]
    float* out_trans = out + (long long)N_CABLE * D;  // [N_TRANS, D]

    const int SMEM_BYTES = (2 * D * WPAD + 2 * MTILE * D) * (int)sizeof(float);
    static bool attr_set = false;
    // setting attributes is idempotent; do it every call (cheap, capture-safe)
    cudaFuncSetAttribute(stageA, cudaFuncAttributeMaxDynamicSharedMemorySize, SMEM_BYTES);
    cudaFuncSetAttribute(stageB, cudaFuncAttributeMaxDynamicSharedMemorySize, SMEM_BYTES);
    (void)attr_set;

    zero_kernel<<<512, 256>>>();
    stageA<<<2048, NTHREADS, SMEM_BYTES>>>(x, abc, w1, b1, w2, b2);
    stageB<<<(N_CABLE + MTILE - 1) / MTILE, NTHREADS, SMEM_BYTES>>>(act, w3, b3, w4, b4, out_cable);
    finalize_trans<<<(N_TRANS * D + 255) / 256, 256>>>(out_trans);
    (void)in_sizes; (void)n_in; (void)out_size;
}

// round 3
// speedup vs baseline: 3.0765x; 3.0765x over previous
#include <cuda_runtime.h>
#include <cuda_bf16.h>
#include <cstdint>

#define N_BUILD 1048576
#define N_CABLE 50000
#define N_TRANS 2000
#define D 128
#define TILE_M 128

// ---------------- device scratch (no allocations allowed) ----------------
__device__ float g_sum_c[N_CABLE * D];
__device__ int   g_cnt_c[N_CABLE];
__device__ float g_sum_t[N_TRANS * D];
__device__ int   g_cnt_t[N_TRANS];

// SMEM layout (byte offsets from 1KB-aligned base): weight tiles [n=128][k=128] bf16,
// row stride 256B, XOR-swizzled 16B chunks for conflict-free ldmatrix.
#define OFF_WAH 0
#define OFF_WAL 32768
#define OFF_WBH 65536
#define OFF_WBL 98304
#define OFF_BA  131072
#define OFF_BB  (OFF_BA + 512)
#define SMEM_DYN (OFF_BB + 512 + 1024)

static __device__ __forceinline__ uint32_t smem_u32(const void* p) {
    uint32_t a;
    asm("{ .reg .u64 t; cvta.to.shared.u64 t, %1; cvt.u32.u64 %0, t; }" : "=r"(a) : "l"(p));
    return a;
}
static __device__ __forceinline__ uint32_t pk_bf16x2(float a, float b) {
    __nv_bfloat162 t(__float2bfloat16(a), __float2bfloat16(b));
    return *(uint32_t*)&t;
}
static __device__ __forceinline__ float bf_hi(float v) {
    return __bfloat162float(__float2bfloat16(v));
}
static __device__ __forceinline__ void ldsm4(uint32_t& r0, uint32_t& r1, uint32_t& r2, uint32_t& r3, uint32_t addr) {
    asm volatile("ldmatrix.sync.aligned.m8n8.x4.shared.b16 {%0,%1,%2,%3}, [%4];"
                 : "=r"(r0), "=r"(r1), "=r"(r2), "=r"(r3) : "r"(addr));
}
static __device__ __forceinline__ void mma16816(float* c, uint32_t a0, uint32_t a1, uint32_t a2, uint32_t a3,
                                                uint32_t b0, uint32_t b1) {
    asm volatile("mma.sync.aligned.m16n8k16.row.col.f32.bf16.bf16.f32 "
                 "{%0,%1,%2,%3}, {%4,%5,%6,%7}, {%8,%9}, {%0,%1,%2,%3};"
                 : "+f"(c[0]), "+f"(c[1]), "+f"(c[2]), "+f"(c[3])
                 : "r"(a0), "r"(a1), "r"(a2), "r"(a3), "r"(b0), "r"(b1));
}
static __device__ __forceinline__ void red_add_v2(float* p, float a, float b) {
    asm volatile("red.global.add.v2.f32 [%0], {%1, %2};" :: "l"(p), "f"(a), "f"(b) : "memory");
}

// ---------------- zero scratch ----------------
__global__ void zero_kernel() {
    int stride = gridDim.x * blockDim.x;
    int t = blockIdx.x * blockDim.x + threadIdx.x;
    for (int i = t; i < N_CABLE * D; i += stride) g_sum_c[i] = 0.0f;
    for (int i = t; i < N_TRANS * D; i += stride) g_sum_t[i] = 0.0f;
    for (int i = t; i < N_CABLE; i += stride) g_cnt_c[i] = 0;
    for (int i = t; i < N_TRANS; i += stride) g_cnt_t[i] = 0;
}

// ---------------- fused 2-layer MLP + scatter-add, HMMA bf16-split ----------------
// MODE 0: x = xin[nrows, 128] fp32, scatter -> g_sum_c / g_cnt_c
// MODE 1: x = g_sum_c / max(g_cnt_c,1) (also written to out_cable), scatter -> g_sum_t / g_cnt_t
template<int MODE>
__global__ __launch_bounds__(256, 1)
void mlp_pool(int nrows, int ntiles,
              const float* __restrict__ xin, const int* __restrict__ idx,
              const float* __restrict__ wA, const float* __restrict__ bA,
              const float* __restrict__ wB, const float* __restrict__ bB,
              float* __restrict__ out_cable) {
    extern __shared__ char smraw[];
    char* sm = (char*)(((uintptr_t)smraw + 1023) & ~(uintptr_t)1023);
    const uint32_t smU = smem_u32(sm);
    float* bAs = (float*)(sm + OFF_BA);
    float* bBs = (float*)(sm + OFF_BB);

    const int tid  = threadIdx.x;
    const int wid  = tid >> 5;
    const int lane = tid & 31;
    const int q    = lane & 3;
    const int rq   = lane >> 2;

    // ---- split + swizzle weights into smem (once per CTA) ----
    // item: 8 consecutive fp32 of one [out]-row -> 16B hi chunk + 16B lo chunk
    for (int i = tid; i < 2 * 128 * 16; i += 256) {
        int m  = i >> 11;          // 0 = layer A, 1 = layer B
        int r  = (i >> 4) & 127;   // output-neuron row
        int kc = i & 15;           // 16B (8-elem) chunk along k
        const float* src = (m ? wB : wA) + r * 128 + kc * 8;
        float4 f0 = *(const float4*)(src);
        float4 f1 = *(const float4*)(src + 4);
        uint4 hi, lo;
        hi.x = pk_bf16x2(f0.x, f0.y); hi.y = pk_bf16x2(f0.z, f0.w);
        hi.z = pk_bf16x2(f1.x, f1.y); hi.w = pk_bf16x2(f1.z, f1.w);
        lo.x = pk_bf16x2(f0.x - bf_hi(f0.x), f0.y - bf_hi(f0.y));
        lo.y = pk_bf16x2(f0.z - bf_hi(f0.z), f0.w - bf_hi(f0.w));
        lo.z = pk_bf16x2(f1.x - bf_hi(f1.x), f1.y - bf_hi(f1.y));
        lo.w = pk_bf16x2(f1.z - bf_hi(f1.z), f1.w - bf_hi(f1.w));
        uint32_t off = (uint32_t)(r * 256 + ((kc ^ (r & 7)) << 4));
        *(uint4*)(sm + (m ? OFF_WBH : OFF_WAH) + off) = hi;
        *(uint4*)(sm + (m ? OFF_WBL : OFF_WAL) + off) = lo;
    }
    for (int i = tid; i < D; i += 256) { bAs[i] = bA[i]; bBs[i] = bB[i]; }
    __syncthreads();

    float* dst = MODE ? g_sum_t : g_sum_c;
    int*   cnt = MODE ? g_cnt_t : g_cnt_c;

    // ldmatrix lane addressing for B (x4 = two n8 tiles): within group g,
    // brow = 16g + browX, k-chunk = 2s + kb
    const int browX = ((lane >> 4) << 3) + (lane & 7);
    const int kb    = (lane >> 3) & 1;

    const int rloc = wid * 16 + rq;   // local row (second row = +8)

    for (int t = blockIdx.x; t < ntiles; t += gridDim.x) {
        const int base = t * TILE_M;
        const int r1 = base + rloc;
        const int r2 = r1 + 8;

        // ---- load X directly into A-fragment-shaped registers ----
        float2 xr[8][4];
        if (MODE == 0) {
            const float* p1 = xin + (size_t)r1 * D;
            const float* p2 = xin + (size_t)r2 * D;
            #pragma unroll
            for (int s = 0; s < 8; s++) {
                int k0 = 16 * s + 2 * q;
                xr[s][0] = *(const float2*)(p1 + k0);
                xr[s][1] = *(const float2*)(p2 + k0);
                xr[s][2] = *(const float2*)(p1 + k0 + 8);
                xr[s][3] = *(const float2*)(p2 + k0 + 8);
            }
        } else {
            float rc1 = 0.f, rc2 = 0.f;
            if (r1 < nrows) rc1 = 1.0f / fmaxf((float)g_cnt_c[r1], 1.0f);
            if (r2 < nrows) rc2 = 1.0f / fmaxf((float)g_cnt_c[r2], 1.0f);
            const float* p1 = g_sum_c + (size_t)r1 * D;
            const float* p2 = g_sum_c + (size_t)r2 * D;
            #pragma unroll
            for (int s = 0; s < 8; s++) {
                int k0 = 16 * s + 2 * q;
                float2 a = make_float2(0.f, 0.f), b = a, c = a, d = a;
                if (r1 < nrows) {
                    float2 v = *(const float2*)(p1 + k0);
                    a.x = v.x * rc1; a.y = v.y * rc1;
                    float2 w = *(const float2*)(p1 + k0 + 8);
                    c.x = w.x * rc1; c.y = w.y * rc1;
                    *(float2*)(out_cable + (size_t)r1 * D + k0) = a;
                    *(float2*)(out_cable + (size_t)r1 * D + k0 + 8) = c;
                }
                if (r2 < nrows) {
                    float2 v = *(const float2*)(p2 + k0);
                    b.x = v.x * rc2; b.y = v.y * rc2;
                    float2 w = *(const float2*)(p2 + k0 + 8);
                    d.x = w.x * rc2; d.y = w.y * rc2;
                    *(float2*)(out_cable + (size_t)r2 * D + k0) = b;
                    *(float2*)(out_cable + (size_t)r2 * D + k0 + 8) = d;
                }
                xr[s][0] = a; xr[s][1] = b; xr[s][2] = c; xr[s][3] = d;
            }
        }

        // ---- layer 1: acc = Xh@Wh + Xh@Wl + Xl@Wh ----
        float acc[16][4];
        #pragma unroll
        for (int j = 0; j < 16; j++)
            { acc[j][0] = 0.f; acc[j][1] = 0.f; acc[j][2] = 0.f; acc[j][3] = 0.f; }

        #pragma unroll
        for (int s = 0; s < 8; s++) {
            uint32_t ah[4], al[4];
            #pragma unroll
            for (int e = 0; e < 4; e++) {
                float2 v = xr[s][e];
                ah[e] = pk_bf16x2(v.x, v.y);
                al[e] = pk_bf16x2(v.x - bf_hi(v.x), v.y - bf_hi(v.y));
            }
            #pragma unroll
            for (int g = 0; g < 8; g++) {
                int brow = 16 * g + browX;
                uint32_t coff = (uint32_t)(((2 * s + kb) ^ (brow & 7)) << 4);
                uint32_t rowb = (uint32_t)(brow * 256);
                uint32_t bh0, bh1, bh2, bh3, bl0, bl1, bl2, bl3;
                ldsm4(bh0, bh1, bh2, bh3, smU + OFF_WAH + rowb + coff);
                ldsm4(bl0, bl1, bl2, bl3, smU + OFF_WAL + rowb + coff);
                mma16816(acc[2*g],   ah[0], ah[1], ah[2], ah[3], bh0, bh1);
                mma16816(acc[2*g],   ah[0], ah[1], ah[2], ah[3], bl0, bl1);
                mma16816(acc[2*g],   al[0], al[1], al[2], al[3], bh0, bh1);
                mma16816(acc[2*g+1], ah[0], ah[1], ah[2], ah[3], bh2, bh3);
                mma16816(acc[2*g+1], ah[0], ah[1], ah[2], ah[3], bl2, bl3);
                mma16816(acc[2*g+1], al[0], al[1], al[2], al[3], bh2, bh3);
            }
        }

        // ---- epilogue 1: H = relu(acc + bA) -> A fragments (registers only) ----
        uint32_t AH[32], AL[32];
        #pragma unroll
        for (int j = 0; j < 16; j++) {
            int col0 = 8 * j + 2 * q;
            float b0 = bAs[col0], b1 = bAs[col0 + 1];
            float v0 = fmaxf(acc[j][0] + b0, 0.f);
            float v1 = fmaxf(acc[j][1] + b1, 0.f);
            float v2 = fmaxf(acc[j][2] + b0, 0.f);
            float v3 = fmaxf(acc[j][3] + b1, 0.f);
            int i0 = (j >> 1) * 4 + (j & 1) * 2;
            AH[i0]     = pk_bf16x2(v0, v1);
            AH[i0 + 1] = pk_bf16x2(v2, v3);
            AL[i0]     = pk_bf16x2(v0 - bf_hi(v0), v1 - bf_hi(v1));
            AL[i0 + 1] = pk_bf16x2(v2 - bf_hi(v2), v3 - bf_hi(v3));
        }

        // ---- layer 2 ----
        #pragma unroll
        for (int j = 0; j < 16; j++)
            { acc[j][0] = 0.f; acc[j][1] = 0.f; acc[j][2] = 0.f; acc[j][3] = 0.f; }

        #pragma unroll
        for (int s = 0; s < 8; s++) {
            #pragma unroll
            for (int g = 0; g < 8; g++) {
                int brow = 16 * g + browX;
                uint32_t coff = (uint32_t)(((2 * s + kb) ^ (brow & 7)) << 4);
                uint32_t rowb = (uint32_t)(brow * 256);
                uint32_t bh0, bh1, bh2, bh3, bl0, bl1, bl2, bl3;
                ldsm4(bh0, bh1, bh2, bh3, smU + OFF_WBH + rowb + coff);
                ldsm4(bl0, bl1, bl2, bl3, smU + OFF_WBL + rowb + coff);
                mma16816(acc[2*g],   AH[4*s], AH[4*s+1], AH[4*s+2], AH[4*s+3], bh0, bh1);
                mma16816(acc[2*g],   AH[4*s], AH[4*s+1], AH[4*s+2], AH[4*s+3], bl0, bl1);
                mma16816(acc[2*g],   AL[4*s], AL[4*s+1], AL[4*s+2], AL[4*s+3], bh0, bh1);
                mma16816(acc[2*g+1], AH[4*s], AH[4*s+1], AH[4*s+2], AH[4*s+3], bh2, bh3);
                mma16816(acc[2*g+1], AH[4*s], AH[4*s+1], AH[4*s+2], AH[4*s+3], bl2, bl3);
                mma16816(acc[2*g+1], AL[4*s], AL[4*s+1], AL[4*s+2], AL[4*s+3], bh2, bh3);
            }
        }

        // ---- epilogue 2: y = acc + bB, scatter ----
        int cid1 = -1, cid2 = -1;
        if (MODE == 0) {
            cid1 = idx[r1];
            cid2 = idx[r2];
        } else {
            if (r1 < nrows) cid1 = idx[r1];
            if (r2 < nrows) cid2 = idx[r2];
        }
        #pragma unroll
        for (int j = 0; j < 16; j++) {
            int col0 = 8 * j + 2 * q;
            float b0 = bBs[col0], b1 = bBs[col0 + 1];
            if (cid1 >= 0) red_add_v2(dst + (size_t)cid1 * D + col0, acc[j][0] + b0, acc[j][1] + b1);
            if (cid2 >= 0) red_add_v2(dst + (size_t)cid2 * D + col0, acc[j][2] + b0, acc[j][3] + b1);
        }
        if (q == 0) {
            if (cid1 >= 0) atomicAdd(cnt + cid1, 1);
            if (cid2 >= 0) atomicAdd(cnt + cid2, 1);
        }
    }
}

// ---------------- finalize: x_trans = g_sum_t / max(cnt,1) ----------------
__global__ void finalize_trans(float* __restrict__ out_trans) {
    int i = blockIdx.x * blockDim.x + threadIdx.x;
    if (i < N_TRANS * D) {
        int row = i >> 7;
        float cnt = fmaxf((float)g_cnt_t[row], 1.0f);
        out_trans[i] = g_sum_t[i] / cnt;
    }
}

extern "C" void kernel_launch(void* const* d_in, const int* in_sizes, int n_in,
                              void* d_out, int out_size) {
    const float* x   = (const float*)d_in[0];
    const int*   abc = (const int*)d_in[1];
    const int*   act = (const int*)d_in[2];
    const float* w1  = (const float*)d_in[3];
    const float* b1  = (const float*)d_in[4];
    const float* w2  = (const float*)d_in[5];
    const float* b2  = (const float*)d_in[6];
    const float* w3  = (const float*)d_in[7];
    const float* b3  = (const float*)d_in[8];
    const float* w4  = (const float*)d_in[9];
    const float* b4  = (const float*)d_in[10];

    float* out = (float*)d_out;
    float* out_cable = out;                        // [N_CABLE, D]
    float* out_trans = out + (size_t)N_CABLE * D;  // [N_TRANS, D]

    cudaFuncSetAttribute(mlp_pool<0>, cudaFuncAttributeMaxDynamicSharedMemorySize, SMEM_DYN);
    cudaFuncSetAttribute(mlp_pool<1>, cudaFuncAttributeMaxDynamicSharedMemorySize, SMEM_DYN);

    const int ntA = N_BUILD / TILE_M;
    const int ntB = (N_CABLE + TILE_M - 1) / TILE_M;

    zero_kernel<<<1024, 256>>>();
    mlp_pool<0><<<152, 256, SMEM_DYN>>>(N_BUILD, ntA, x, abc, w1, b1, w2, b2, nullptr);
    mlp_pool<1><<<152, 256, SMEM_DYN>>>(N_CABLE, ntB, nullptr, act, w3, b3, w4, b4, out_cable);
    finalize_trans<<<(N_TRANS * D + 255) / 256, 256>>>(out_trans);
    (void)in_sizes; (void)n_in; (void)out_size;
}

// round 5
// speedup vs baseline: 3.2630x; 1.0606x over previous
#include <cuda_runtime.h>
#include <cuda_bf16.h>
#include <cstdint>

#define N_BUILD 1048576
#define N_CABLE 50000
#define N_TRANS 2000
#define D 128
#define TILE_M 256   // 8 warps x 32 rows

// ---------------- device scratch (no allocations allowed) ----------------
__device__ float g_sum_c[N_CABLE * D];
__device__ int   g_cnt_c[N_CABLE];
__device__ float g_sum_t[N_TRANS * D];
__device__ int   g_cnt_t[N_TRANS];

// SMEM: weight tiles [n=128][k=128] bf16, row stride 256B, XOR-swizzled 16B chunks.
#define OFF_WAH 0
#define OFF_WAL 32768
#define OFF_WBH 65536
#define OFF_WBL 98304
#define OFF_BA  131072
#define OFF_BB  (OFF_BA + 512)
#define SMEM_DYN (OFF_BB + 512 + 1024)

static __device__ __forceinline__ uint32_t smem_u32(const void* p) {
    uint32_t a;
    asm("{ .reg .u64 t; cvta.to.shared.u64 t, %1; cvt.u32.u64 %0, t; }" : "=r"(a) : "l"(p));
    return a;
}
static __device__ __forceinline__ uint32_t pk_bf16x2(float a, float b) {
    __nv_bfloat162 t(__float2bfloat16(a), __float2bfloat16(b));
    return *(uint32_t*)&t;
}
static __device__ __forceinline__ float bf_hi(float v) {
    return __bfloat162float(__float2bfloat16(v));
}
static __device__ __forceinline__ void ldsm4(uint32_t& r0, uint32_t& r1, uint32_t& r2, uint32_t& r3, uint32_t addr) {
    asm volatile("ldmatrix.sync.aligned.m8n8.x4.shared.b16 {%0,%1,%2,%3}, [%4];"
                 : "=r"(r0), "=r"(r1), "=r"(r2), "=r"(r3) : "r"(addr));
}
static __device__ __forceinline__ void mma16816(float* c, const uint32_t* a, uint32_t b0, uint32_t b1) {
    asm volatile("mma.sync.aligned.m16n8k16.row.col.f32.bf16.bf16.f32 "
                 "{%0,%1,%2,%3}, {%4,%5,%6,%7}, {%8,%9}, {%0,%1,%2,%3};"
                 : "+f"(c[0]), "+f"(c[1]), "+f"(c[2]), "+f"(c[3])
                 : "r"(a[0]), "r"(a[1]), "r"(a[2]), "r"(a[3]), "r"(b0), "r"(b1));
}
static __device__ __forceinline__ void red_add_v4(float* p, float a, float b, float c, float d) {
    asm volatile("red.global.add.v4.f32 [%0], {%1, %2, %3, %4};"
                 :: "l"(p), "f"(a), "f"(b), "f"(c), "f"(d) : "memory");
}

// ---------------- zero scratch ----------------
__global__ void zero_kernel() {
    int stride = gridDim.x * blockDim.x;
    int t = blockIdx.x * blockDim.x + threadIdx.x;
    float4 z = make_float4(0.f, 0.f, 0.f, 0.f);
    for (int i = t; i < N_CABLE * D / 4; i += stride) ((float4*)g_sum_c)[i] = z;
    for (int i = t; i < N_TRANS * D / 4; i += stride) ((float4*)g_sum_t)[i] = z;
    for (int i = t; i < N_CABLE; i += stride) g_cnt_c[i] = 0;
    for (int i = t; i < N_TRANS; i += stride) g_cnt_t[i] = 0;
}

// ---------------- fused 2-layer MLP + scatter-add, HMMA bf16-split, M=32/warp ----------------
template<int MODE>
__global__ __launch_bounds__(256, 1)
void mlp_pool(int nrows, int ntiles,
              const float* __restrict__ xin, const int* __restrict__ idx,
              const float* __restrict__ wA, const float* __restrict__ bA,
              const float* __restrict__ wB, const float* __restrict__ bB,
              float* __restrict__ out_cable) {
    extern __shared__ char smraw[];
    char* sm = (char*)(((uintptr_t)smraw + 1023) & ~(uintptr_t)1023);
    const uint32_t smU = smem_u32(sm);
    float* bAs = (float*)(sm + OFF_BA);
    float* bBs = (float*)(sm + OFF_BB);

    const int tid  = threadIdx.x;
    const int wid  = tid >> 5;
    const int lane = tid & 31;
    const int q    = lane & 3;
    const int rq   = lane >> 2;

    // ---- split + swizzle weights into smem (once per CTA) ----
    for (int i = tid; i < 2 * 128 * 16; i += 256) {
        int m  = i >> 11;
        int r  = (i >> 4) & 127;
        int kc = i & 15;
        const float* src = (m ? wB : wA) + r * 128 + kc * 8;
        float4 f0 = *(const float4*)(src);
        float4 f1 = *(const float4*)(src + 4);
        uint4 hi, lo;
        hi.x = pk_bf16x2(f0.x, f0.y); hi.y = pk_bf16x2(f0.z, f0.w);
        hi.z = pk_bf16x2(f1.x, f1.y); hi.w = pk_bf16x2(f1.z, f1.w);
        lo.x = pk_bf16x2(f0.x - bf_hi(f0.x), f0.y - bf_hi(f0.y));
        lo.y = pk_bf16x2(f0.z - bf_hi(f0.z), f0.w - bf_hi(f0.w));
        lo.z = pk_bf16x2(f1.x - bf_hi(f1.x), f1.y - bf_hi(f1.y));
        lo.w = pk_bf16x2(f1.z - bf_hi(f1.z), f1.w - bf_hi(f1.w));
        uint32_t off = (uint32_t)(r * 256 + ((kc ^ (r & 7)) << 4));
        *(uint4*)(sm + (m ? OFF_WBH : OFF_WAH) + off) = hi;
        *(uint4*)(sm + (m ? OFF_WBL : OFF_WAL) + off) = lo;
    }
    for (int i = tid; i < D; i += 256) { bAs[i] = bA[i]; bBs[i] = bB[i]; }
    __syncthreads();

    float* dst = MODE ? g_sum_t : g_sum_c;
    int*   cnt = MODE ? g_cnt_t : g_cnt_c;

    const int browX = ((lane >> 4) << 3) + (lane & 7);
    const int kb    = (lane >> 3) & 1;

    for (int t = blockIdx.x; t < ntiles; t += gridDim.x) {
        const int base = t * TILE_M + wid * 32;
        // rows per thread: half h in {0,1}: rA = base + 16h + rq, rB = rA + 8
        int rA[2], rB[2], cidA[2], cidB[2];
        float rcA[2], rcB[2];
        #pragma unroll
        for (int h = 0; h < 2; h++) {
            rA[h] = base + 16 * h + rq;
            rB[h] = rA[h] + 8;
            if (MODE == 0) {
                cidA[h] = idx[rA[h]];
                cidB[h] = idx[rB[h]];
            } else {
                cidA[h] = (rA[h] < nrows) ? idx[rA[h]] : -1;
                cidB[h] = (rB[h] < nrows) ? idx[rB[h]] : -1;
                rcA[h] = (rA[h] < nrows) ? 1.0f / fmaxf((float)g_cnt_c[rA[h]], 1.0f) : 0.f;
                rcB[h] = (rB[h] < nrows) ? 1.0f / fmaxf((float)g_cnt_c[rB[h]], 1.0f) : 0.f;
            }
        }

        // ================= layer 1 (s-outer, full acc) =================
        float acc[2][16][4];
        #pragma unroll
        for (int h = 0; h < 2; h++)
            #pragma unroll
            for (int j = 0; j < 16; j++)
                { acc[h][j][0] = 0.f; acc[h][j][1] = 0.f; acc[h][j][2] = 0.f; acc[h][j][3] = 0.f; }

        #pragma unroll
        for (int s = 0; s < 8; s++) {
            const int k0 = 16 * s + 2 * q;
            uint32_t ah[2][4], al[2][4];
            #pragma unroll
            for (int h = 0; h < 2; h++) {
                float2 va, vb, vc, vd;
                if (MODE == 0) {
                    const float* p1 = xin + (size_t)rA[h] * D;
                    const float* p2 = xin + (size_t)rB[h] * D;
                    va = *(const float2*)(p1 + k0);
                    vb = *(const float2*)(p2 + k0);
                    vc = *(const float2*)(p1 + k0 + 8);
                    vd = *(const float2*)(p2 + k0 + 8);
                } else {
                    va = vb = vc = vd = make_float2(0.f, 0.f);
                    if (rA[h] < nrows) {
                        const float* p1 = g_sum_c + (size_t)rA[h] * D;
                        float2 v = *(const float2*)(p1 + k0);
                        va.x = v.x * rcA[h]; va.y = v.y * rcA[h];
                        float2 w = *(const float2*)(p1 + k0 + 8);
                        vc.x = w.x * rcA[h]; vc.y = w.y * rcA[h];
                        *(float2*)(out_cable + (size_t)rA[h] * D + k0) = va;
                        *(float2*)(out_cable + (size_t)rA[h] * D + k0 + 8) = vc;
                    }
                    if (rB[h] < nrows) {
                        const float* p2 = g_sum_c + (size_t)rB[h] * D;
                        float2 v = *(const float2*)(p2 + k0);
                        vb.x = v.x * rcB[h]; vb.y = v.y * rcB[h];
                        float2 w = *(const float2*)(p2 + k0 + 8);
                        vd.x = w.x * rcB[h]; vd.y = w.y * rcB[h];
                        *(float2*)(out_cable + (size_t)rB[h] * D + k0) = vb;
                        *(float2*)(out_cable + (size_t)rB[h] * D + k0 + 8) = vd;
                    }
                }
                ah[h][0] = pk_bf16x2(va.x, va.y);
                ah[h][1] = pk_bf16x2(vb.x, vb.y);
                ah[h][2] = pk_bf16x2(vc.x, vc.y);
                ah[h][3] = pk_bf16x2(vd.x, vd.y);
                al[h][0] = pk_bf16x2(va.x - bf_hi(va.x), va.y - bf_hi(va.y));
                al[h][1] = pk_bf16x2(vb.x - bf_hi(vb.x), vb.y - bf_hi(vb.y));
                al[h][2] = pk_bf16x2(vc.x - bf_hi(vc.x), vc.y - bf_hi(vc.y));
                al[h][3] = pk_bf16x2(vd.x - bf_hi(vd.x), vd.y - bf_hi(vd.y));
            }
            #pragma unroll
            for (int g = 0; g < 8; g++) {
                int brow = 16 * g + browX;
                uint32_t a0 = smU + (uint32_t)(brow * 256 + (((2 * s + kb) ^ (brow & 7)) << 4));
                uint32_t bh0, bh1, bh2, bh3, bl0, bl1, bl2, bl3;
                ldsm4(bh0, bh1, bh2, bh3, a0 + OFF_WAH);
                ldsm4(bl0, bl1, bl2, bl3, a0 + OFF_WAL);
                #pragma unroll
                for (int h = 0; h < 2; h++) {
                    mma16816(acc[h][2*g],   ah[h], bh0, bh1);
                    mma16816(acc[h][2*g],   ah[h], bl0, bl1);
                    mma16816(acc[h][2*g],   al[h], bh0, bh1);
                    mma16816(acc[h][2*g+1], ah[h], bh2, bh3);
                    mma16816(acc[h][2*g+1], ah[h], bl2, bl3);
                    mma16816(acc[h][2*g+1], al[h], bh2, bh3);
                }
            }
        }

        // ---- transition: H = relu(acc + bA) -> packed A fragments ----
        uint32_t AH[2][32], AL[2][32];
        #pragma unroll
        for (int h = 0; h < 2; h++) {
            #pragma unroll
            for (int j = 0; j < 16; j++) {
                int col0 = 8 * j + 2 * q;
                float b0 = bAs[col0], b1 = bAs[col0 + 1];
                float v0 = fmaxf(acc[h][j][0] + b0, 0.f);
                float v1 = fmaxf(acc[h][j][1] + b1, 0.f);
                float v2 = fmaxf(acc[h][j][2] + b0, 0.f);
                float v3 = fmaxf(acc[h][j][3] + b1, 0.f);
                int i0 = (j >> 1) * 4 + (j & 1) * 2;
                AH[h][i0]     = pk_bf16x2(v0, v1);
                AH[h][i0 + 1] = pk_bf16x2(v2, v3);
                AL[h][i0]     = pk_bf16x2(v0 - bf_hi(v0), v1 - bf_hi(v1));
                AL[h][i0 + 1] = pk_bf16x2(v2 - bf_hi(v2), v3 - bf_hi(v3));
            }
        }

        // ================= layer 2 (g-outer, scatter per chunk) =================
        #pragma unroll
        for (int g = 0; g < 8; g++) {
            float a2[2][2][4];
            #pragma unroll
            for (int h = 0; h < 2; h++)
                #pragma unroll
                for (int tt = 0; tt < 2; tt++)
                    { a2[h][tt][0] = 0.f; a2[h][tt][1] = 0.f; a2[h][tt][2] = 0.f; a2[h][tt][3] = 0.f; }

            #pragma unroll
            for (int s = 0; s < 8; s++) {
                int brow = 16 * g + browX;
                uint32_t a0 = smU + (uint32_t)(brow * 256 + (((2 * s + kb) ^ (brow & 7)) << 4));
                uint32_t bh0, bh1, bh2, bh3, bl0, bl1, bl2, bl3;
                ldsm4(bh0, bh1, bh2, bh3, a0 + OFF_WBH);
                ldsm4(bl0, bl1, bl2, bl3, a0 + OFF_WBL);
                #pragma unroll
                for (int h = 0; h < 2; h++) {
                    mma16816(a2[h][0], &AH[h][4*s], bh0, bh1);
                    mma16816(a2[h][0], &AH[h][4*s], bl0, bl1);
                    mma16816(a2[h][0], &AL[h][4*s], bh0, bh1);
                    mma16816(a2[h][1], &AH[h][4*s], bh2, bh3);
                    mma16816(a2[h][1], &AH[h][4*s], bl2, bl3);
                    mma16816(a2[h][1], &AL[h][4*s], bh2, bh3);
                }
            }
            // scatter cols [16g, 16g+16) for 32 rows; lane-pair exchange -> red.v4
            #pragma unroll
            for (int h = 0; h < 2; h++) {
                #pragma unroll
                for (int tt = 0; tt < 2; tt++) {
                    int col0 = 16 * g + 8 * tt + 2 * q;
                    float b0 = bBs[col0], b1 = bBs[col0 + 1];
                    float v0 = a2[h][tt][0] + b0;
                    float v1 = a2[h][tt][1] + b1;
                    float v2 = a2[h][tt][2] + b0;
                    float v3 = a2[h][tt][3] + b1;
                    float e0 = __shfl_xor_sync(0xffffffffu, v0, 1);
                    float e1 = __shfl_xor_sync(0xffffffffu, v1, 1);
                    float e2 = __shfl_xor_sync(0xffffffffu, v2, 1);
                    float e3 = __shfl_xor_sync(0xffffffffu, v3, 1);
                    if ((lane & 1) == 0) {
                        if (cidA[h] >= 0)
                            red_add_v4(dst + (size_t)cidA[h] * D + col0, v0, v1, e0, e1);
                    } else {
                        if (cidB[h] >= 0)
                            red_add_v4(dst + (size_t)cidB[h] * D + col0 - 2, e2, e3, v2, v3);
                    }
                }
            }
        }
        if (q == 0) {
            #pragma unroll
            for (int h = 0; h < 2; h++) {
                if (cidA[h] >= 0) atomicAdd(cnt + cidA[h], 1);
                if (cidB[h] >= 0) atomicAdd(cnt + cidB[h], 1);
            }
        }
    }
}

// ---------------- finalize: x_trans = g_sum_t / max(cnt,1) ----------------
__global__ void finalize_trans(float* __restrict__ out_trans) {
    int i = blockIdx.x * blockDim.x + threadIdx.x;
    if (i < N_TRANS * D) {
        int row = i >> 7;
        float cnt = fmaxf((float)g_cnt_t[row], 1.0f);
        out_trans[i] = g_sum_t[i] / cnt;
    }
}

extern "C" void kernel_launch(void* const* d_in, const int* in_sizes, int n_in,
                              void* d_out, int out_size) {
    const float* x   = (const float*)d_in[0];
    const int*   abc = (const int*)d_in[1];
    const int*   act = (const int*)d_in[2];
    const float* w1  = (const float*)d_in[3];
    const float* b1  = (const float*)d_in[4];
    const float* w2  = (const float*)d_in[5];
    const float* b2  = (const float*)d_in[6];
    const float* w3  = (const float*)d_in[7];
    const float* b3  = (const float*)d_in[8];
    const float* w4  = (const float*)d_in[9];
    const float* b4  = (const float*)d_in[10];

    float* out = (float*)d_out;
    float* out_cable = out;                        // [N_CABLE, D]
    float* out_trans = out + (size_t)N_CABLE * D;  // [N_TRANS, D]

    cudaFuncSetAttribute(mlp_pool<0>, cudaFuncAttributeMaxDynamicSharedMemorySize, SMEM_DYN);
    cudaFuncSetAttribute(mlp_pool<1>, cudaFuncAttributeMaxDynamicSharedMemorySize, SMEM_DYN);

    const int ntA = N_BUILD / TILE_M;
    const int ntB = (N_CABLE + TILE_M - 1) / TILE_M;

    zero_kernel<<<1024, 256>>>();
    mlp_pool<0><<<152, 256, SMEM_DYN>>>(N_BUILD, ntA, x, abc, w1, b1, w2, b2, nullptr);
    mlp_pool<1><<<152, 256, SMEM_DYN>>>(N_CABLE, ntB, nullptr, act, w3, b3, w4, b4, out_cable);
    finalize_trans<<<(N_TRANS * D + 255) / 256, 256>>>(out_trans);
    (void)in_sizes; (void)n_in; (void)out_size;
}